// round 13
// baseline (speedup 1.0000x reference)
#include <cuda_runtime.h>

// ---------------------------------------------------------------------------
// DECOLA Stage2 assigner — single kernel, one block per (label, batch) bucket.
//
// Key fact: match = (gt_label == prompt_ind), so the entire assignment
// decomposes per (batch,label) bucket: a GT only ever interacts with
// proposals of its own label, best_gt for a proposal is within its label's
// GTs, and each GT's output row is produced by exactly one bucket. Hence one
// self-contained block per bucket, chip-wide grid (128x16 = 2048 blocks),
// zero global scratch, zero inter-kernel traffic, ONE launch.
//
// Inputs (metadata order):
//   0: pred_logits_match (B,N,1) f32   -- unused
//   1: pred_boxes        (B,N,4) f32   -- unused
//   2: init_reference    (B,N,4) f32   -- proposals (cxcywh)
//   3: prompt_inds       (B,N)   i32
//   4: gt_labels         (B,M)   i32
//   5: gt_boxes          (B,M,4) f32
//   6: max_k             scalar  i32   (k derived from out_size)
// Output: concat(rows, cols, valid, sel_iou) each (B,M,k), float32.
// ---------------------------------------------------------------------------

#define BB      16            // batch (fixed for this problem)
#define NL      128           // label slots (L=80 < 128)
#define PCAP    192           // proposals per bucket cap (mean 37.5, sd 6 -> 25 sigma)
#define GCAP    32            // gts per bucket cap (mean 3.75, sd 1.9)
#define TOPK    4
#define THREADS 128
#define IMAXI   0x7fffffff

// IoU from explicit _rn intrinsics. Rows pass and cols pass call this same
// function on the SAME smem-resident box bits, so lq's (v == gmax) equality
// is exact by construction.
__device__ __forceinline__ float iou_fn(float4 g, float ga, float4 p, float pa) {
    float x0 = fmaxf(g.x, p.x);
    float y0 = fmaxf(g.y, p.y);
    float x1 = fminf(g.z, p.z);
    float y1 = fminf(g.w, p.w);
    float w  = fmaxf(__fsub_rn(x1, x0), 0.0f);
    float h  = fmaxf(__fsub_rn(y1, y0), 0.0f);
    float it = __fmul_rn(w, h);
    float un = __fsub_rn(__fadd_rn(ga, pa), it);
    return __fdiv_rn(it, fmaxf(un, 1e-9f));
}

// BRANCHLESS insert of (v,i) into a 4-entry list sorted by (value desc,
// index asc): compare-carry chain, pure setp/sel. Strict total order
// (indices distinct) -> insert-order independent; matches jax.lax.top_k
// stability (lower index first among equal values).
__device__ __forceinline__ void ins4(float v, int i, float tv[TOPK], int ti[TOPK]) {
#pragma unroll
    for (int j = 0; j < TOPK; j++) {
        bool sw = (v > tv[j]) || (v == tv[j] && i < ti[j]);
        float cv = sw ? tv[j] : v;
        int   ci = sw ? ti[j] : i;
        tv[j] = sw ? v : tv[j];
        ti[j] = sw ? i : ti[j];
        v = cv; i = ci;
    }
}

__device__ __forceinline__ float4 cxcywh_to_xyxy(float4 c) {
    float4 x;
    x.x = c.x - 0.5f * c.z; x.y = c.y - 0.5f * c.w;
    x.z = c.x + 0.5f * c.z; x.w = c.y + 0.5f * c.w;
    return x;
}

__global__ __launch_bounds__(THREADS)
void k_bucket(const float4* __restrict__ props,
              const float4* __restrict__ gts,
              const int*    __restrict__ pinds,
              const int*    __restrict__ glabels,
              float*        __restrict__ out,
              int N, int M, int B, int K) {
    __shared__ int    s_pcnt, s_gcnt;
    __shared__ int    s_pn  [PCAP];   // proposal indices n
    __shared__ float4 s_pbox[PCAP];
    __shared__ float  s_pa  [PCAP];
    __shared__ int    s_gm  [GCAP];   // gt indices m
    __shared__ float4 s_gbox[GCAP];
    __shared__ float  s_ga  [GCAP];
    __shared__ float  s_gmax[GCAP];
    __shared__ float  s_tv  [GCAP * TOPK];
    __shared__ int    s_ti  [GCAP * TOPK];
    __shared__ int    s_cnt [GCAP];

    const int l   = blockIdx.x;       // label
    const int b   = blockIdx.y;       // batch
    const int tid = threadIdx.x;

    if (tid == 0) { s_pcnt = 0; s_gcnt = 0; }
    __syncthreads();

    // ---- scan gt labels; early-exit if this label has no GT ----
    for (int m = tid; m < M; m += THREADS) {
        if (glabels[b * M + m] == l) {
            int s = atomicAdd(&s_gcnt, 1);
            if (s < GCAP) s_gm[s] = m;
        }
    }
    __syncthreads();
    int gcnt = min(s_gcnt, GCAP);
    if (gcnt == 0) return;            // no GT of this label: no outputs here

    // ---- scan prompt_inds for matching proposals (coalesced, L2-broadcast) ----
    for (int n = tid; n < N; n += THREADS) {
        if (pinds[b * N + n] == l) {
            int s = atomicAdd(&s_pcnt, 1);
            if (s < PCAP) s_pn[s] = n;
        }
    }
    __syncthreads();
    int pcnt = min(s_pcnt, PCAP);

    // ---- load + convert matched boxes into smem (each read exactly once chip-wide) ----
    for (int i = tid; i < pcnt; i += THREADS) {
        float4 x = cxcywh_to_xyxy(props[b * N + s_pn[i]]);
        s_pbox[i] = x;
        s_pa [i]  = __fmul_rn(__fsub_rn(x.z, x.x), __fsub_rn(x.w, x.y));
    }
    for (int i = tid; i < gcnt; i += THREADS) {
        float4 x = cxcywh_to_xyxy(gts[b * M + s_gm[i]]);
        s_gbox[i] = x;
        s_ga [i]  = __fmul_rn(__fsub_rn(x.z, x.x), __fsub_rn(x.w, x.y));
        s_cnt[i]  = 0;
    }
    __syncthreads();

    // ---- rows pass: one warp per GT, lanes stride proposals, butterfly top-4 ----
    {
        int w    = tid >> 5;
        int lane = tid & 31;
        for (int g = w; g < gcnt; g += THREADS / 32) {   // warp-uniform trip count
            float4 gb = s_gbox[g];
            float  ga = s_ga[g];
            float tv[TOPK] = {-1.f, -1.f, -1.f, -1.f};
            int   ti[TOPK] = {IMAXI, IMAXI, IMAXI, IMAXI};
            for (int e = lane; e < pcnt; e += 32) {
                float v = iou_fn(gb, ga, s_pbox[e], s_pa[e]);
                ins4(v, s_pn[e], tv, ti);
            }
#pragma unroll
            for (int off = 16; off > 0; off >>= 1) {
                float ov[TOPK]; int oi[TOPK];
#pragma unroll
                for (int j = 0; j < TOPK; j++) {
                    ov[j] = __shfl_xor_sync(0xffffffffu, tv[j], off);
                    oi[j] = __shfl_xor_sync(0xffffffffu, ti[j], off);
                }
#pragma unroll
                for (int j = 0; j < TOPK; j++) ins4(ov[j], oi[j], tv, ti);
            }
            if (lane == 0) {
                s_gmax[g] = tv[0];        // -1 when bucket has no proposals (== ref NEG)
#pragma unroll
                for (int j = 0; j < TOPK; j++) {
                    s_tv[g * TOPK + j] = tv[j];
                    s_ti[g * TOPK + j] = ti[j];
                }
            }
        }
    }
    __syncthreads();

    // ---- cols pass: per matched proposal, argmax over bucket GTs + lq + counts ----
    for (int i = tid; i < pcnt; i += THREADS) {
        float4 p  = s_pbox[i];
        float  pa = s_pa[i];
        float best = -2.0f;
        int   bgm  = IMAXI;   // gt index m for tie-break (JAX first-index argmax)
        int   bgs  = 0;       // gt slot for s_cnt
        bool  lq   = false;
        for (int e = 0; e < gcnt; e++) {
            float v = iou_fn(s_gbox[e], s_ga[e], p, pa);
            int   m = s_gm[e];
            // lexicographic (v desc, m asc): equals first-index argmax over
            // matched rows; unmatched rows (-1) never beat a matched iou>=0,
            // and pos=false when no match exists (handled by bucket scoping).
            bool bt = (v > best) || (v == best && m < bgm);
            best = bt ? v : best;
            bgm  = bt ? m : bgm;
            bgs  = bt ? e : bgs;
            lq   = lq || (v == s_gmax[e]);    // bitwise: same fn, same smem bits
        }
        if (best >= 0.6f || lq) atomicAdd(&s_cnt[bgs], 1);
    }
    __syncthreads();

    // ---- output: rows | cols | valid | sel_iou for this bucket's GTs ----
    {
        int S = B * M * K;
        for (int e = tid; e < gcnt * K; e += THREADS) {
            int  g    = e / K;
            int  j    = e - g * K;
            int  m    = s_gm[g];
            bool val  = j < min(s_cnt[g], K);
            int  o    = (b * M + m) * K + j;
            out[        o] = val ? (float)s_ti[g * TOPK + j] : -1.0f;
            out[    S + o] = val ? (float)m                  : -1.0f;
            out[2 * S + o] = val ? 1.0f : 0.0f;
            out[3 * S + o] = val ? s_tv[g * TOPK + j]        : 0.0f;
        }
    }
}

// ---------------------------------------------------------------------------
extern "C" void kernel_launch(void* const* d_in, const int* in_sizes, int n_in,
                              void* d_out, int out_size) {
    const float4* props   = (const float4*)d_in[2];
    const int*    pinds   = (const int*)   d_in[3];
    const int*    glabels = (const int*)   d_in[4];
    const float4* gts     = (const float4*)d_in[5];

    const int B  = BB;
    int BN = in_sizes[3];
    int BM = in_sizes[4];
    int N  = BN / B;
    int M  = BM / B;
    int K  = out_size / (4 * BM);
    if (K > TOPK) K = TOPK;
    if (K < 1)    K = 1;

    k_bucket<<<dim3(NL, B), THREADS>>>(props, gts, pinds, glabels,
                                       (float*)d_out, N, M, B, K);
}